// round 3
// baseline (speedup 1.0000x reference)
#include <cuda_runtime.h>
#include <cstdint>

// ---------------------------------------------------------------------------
// DCAELiteMLA: qkv 1x1 conv -> (dw5x5 + grouped pw, fused) -> linear attention
//              -> proj 1x1 conv + residual.
// B=4, C=512, H=W=64 (HW=4096), td=512, DIM=8, heads=128, GROUPS_PW=192.
// ---------------------------------------------------------------------------

#define BATCH 4
#define HW    4096
#define TD3   1536          // 3*td
#define HEADS 128

// Scratch (allocation-free rule: __device__ globals)
__device__ float g_qkv[(size_t)BATCH * TD3 * HW];   // 96 MB
__device__ float g_agg[(size_t)BATCH * TD3 * HW];   // 96 MB
__device__ float g_att[(size_t)BATCH * 1024 * HW];  // 64 MB

// ---------------------------------------------------------------------------
// SGEMM: C[b] = A (MxK, row-major, shared over batch) @ B[b] (KxN, row-major)
// optional residual R[b] (MxN) added. 128x128 tile, BK=8, 256 thr, 8x8/thread.
// Requires M%128==0, N%128==0, K%8==0.
// ---------------------------------------------------------------------------
__global__ __launch_bounds__(256)
void sgemm_kernel(const float* __restrict__ A, const float* __restrict__ B,
                  float* __restrict__ C, const float* __restrict__ R,
                  int M, int N, int K)
{
    __shared__ float As[8][128];
    __shared__ float Bs[8][128];

    const int tid = threadIdx.x;
    const int tx  = tid & 15;       // 16 thread cols
    const int ty  = tid >> 4;       // 16 thread rows
    const size_t bz = blockIdx.z;

    const float* Ab = A + (size_t)blockIdx.y * 128 * K;
    const float* Bb = B + bz * (size_t)K * N + (size_t)blockIdx.x * 128;
    float*       Cb = C + bz * (size_t)M * N
                        + (size_t)blockIdx.y * 128 * N + (size_t)blockIdx.x * 128;
    const float* Rb = R ? (R + bz * (size_t)M * N
                        + (size_t)blockIdx.y * 128 * N + (size_t)blockIdx.x * 128)
                        : nullptr;

    const int aRow = tid >> 1;            // 0..127
    const int aCol = (tid & 1) * 4;       // 0 or 4
    const int bRow = tid >> 5;            // 0..7
    const int bCol = (tid & 31) * 4;      // 0..124

    float acc[8][8];
#pragma unroll
    for (int i = 0; i < 8; i++)
#pragma unroll
        for (int j = 0; j < 8; j++) acc[i][j] = 0.f;

    for (int k0 = 0; k0 < K; k0 += 8) {
        float4 a4 = *(const float4*)(Ab + (size_t)aRow * K + k0 + aCol);
        As[aCol + 0][aRow] = a4.x;
        As[aCol + 1][aRow] = a4.y;
        As[aCol + 2][aRow] = a4.z;
        As[aCol + 3][aRow] = a4.w;
        *(float4*)&Bs[bRow][bCol] =
            *(const float4*)(Bb + (size_t)(k0 + bRow) * N + bCol);
        __syncthreads();

#pragma unroll
        for (int kk = 0; kk < 8; kk++) {
            float ar[8], br[8];
            *(float4*)&ar[0] = *(const float4*)&As[kk][ty * 4];
            *(float4*)&ar[4] = *(const float4*)&As[kk][64 + ty * 4];
            *(float4*)&br[0] = *(const float4*)&Bs[kk][tx * 4];
            *(float4*)&br[4] = *(const float4*)&Bs[kk][64 + tx * 4];
#pragma unroll
            for (int i = 0; i < 8; i++)
#pragma unroll
                for (int j = 0; j < 8; j++)
                    acc[i][j] += ar[i] * br[j];
        }
        __syncthreads();
    }

#pragma unroll
    for (int i = 0; i < 8; i++) {
        int row = (i < 4) ? (ty * 4 + i) : (64 + ty * 4 + (i - 4));
        float* crow = Cb + (size_t)row * N;
        float4 o0 = make_float4(acc[i][0], acc[i][1], acc[i][2], acc[i][3]);
        float4 o1 = make_float4(acc[i][4], acc[i][5], acc[i][6], acc[i][7]);
        if (Rb) {
            const float* rrow = Rb + (size_t)row * N;
            float4 r0 = *(const float4*)(rrow + tx * 4);
            float4 r1 = *(const float4*)(rrow + 64 + tx * 4);
            o0.x += r0.x; o0.y += r0.y; o0.z += r0.z; o0.w += r0.w;
            o1.x += r1.x; o1.y += r1.y; o1.z += r1.z; o1.w += r1.w;
        }
        *(float4*)(crow + tx * 4)      = o0;
        *(float4*)(crow + 64 + tx * 4) = o1;
    }
}

// ---------------------------------------------------------------------------
// Fused depthwise 5x5 (pad=2) + grouped 1x1 (groups=192, 8 in -> 8 out).
// One block = (b, group g, 16x16 spatial tile). Never materializes dw output.
// ---------------------------------------------------------------------------
__global__ __launch_bounds__(256)
void dwpw_kernel(const float* __restrict__ qkv, const float* __restrict__ wdw,
                 const float* __restrict__ wpw, float* __restrict__ agg)
{
    __shared__ float s_in[8][20][20];
    __shared__ float s_wdw[8][25];
    __shared__ float s_wpw[8][8];

    const int tid = threadIdx.y * 16 + threadIdx.x;
    const int bz  = blockIdx.z;
    const int b   = bz / 192;
    const int g   = bz - b * 192;
    const int x0  = blockIdx.x * 16;
    const int y0  = blockIdx.y * 16;

    const float* inb = qkv + ((size_t)b * TD3 + (size_t)g * 8) * HW;

    for (int i = tid; i < 8 * 25; i += 256)
        s_wdw[i / 25][i % 25] = wdw[(g * 8 + i / 25) * 25 + (i % 25)];
    if (tid < 64)
        s_wpw[tid >> 3][tid & 7] = wpw[(g * 8 + (tid >> 3)) * 8 + (tid & 7)];

    for (int idx = tid; idx < 8 * 400; idx += 256) {
        int c  = idx / 400;
        int p  = idx - c * 400;
        int iy = p / 20;
        int ix = p - iy * 20;
        int gy = y0 + iy - 2;
        int gx = x0 + ix - 2;
        float v = 0.f;
        if (gy >= 0 && gy < 64 && gx >= 0 && gx < 64)
            v = inb[(size_t)c * HW + gy * 64 + gx];
        s_in[c][iy][ix] = v;
    }
    __syncthreads();

    const int txx = threadIdx.x, tyy = threadIdx.y;
    float dw[8];
#pragma unroll
    for (int c = 0; c < 8; c++) {
        float s = 0.f;
#pragma unroll
        for (int dy = 0; dy < 5; dy++)
#pragma unroll
            for (int dx = 0; dx < 5; dx++)
                s += s_wdw[c][dy * 5 + dx] * s_in[c][tyy + dy][txx + dx];
        dw[c] = s;
    }

    float* outb = agg + ((size_t)b * TD3 + (size_t)g * 8) * HW
                      + (y0 + tyy) * 64 + (x0 + txx);
#pragma unroll
    for (int o = 0; o < 8; o++) {
        float s = 0.f;
#pragma unroll
        for (int i = 0; i < 8; i++) s += s_wpw[o][i] * dw[i];
        outb[(size_t)o * HW] = s;
    }
}

// ---------------------------------------------------------------------------
// Linear attention per (b, head):
//   q = relu(slots 0..7), k = relu(slots 8..15), v = slots 16..23
//   vk[d][e] = sum_n v_d[n] k_e[n]   (d<8);  vk[8][e] = sum_n k_e[n]
//   out_d[n] = (sum_e vk[d][e] q_e[n]) / (sum_e vk[8][e] q_e[n] + 1e-15)
// Head h<64 reads from g_qkv (chans 24h..), h>=64 from g_agg (chans 24(h-64)..)
// ---------------------------------------------------------------------------
__global__ __launch_bounds__(256)
void attn_kernel(const float* __restrict__ qkvbuf, const float* __restrict__ aggbuf,
                 float* __restrict__ att)
{
    const int bh = blockIdx.x;            // 0..511
    const int b  = bh >> 7;
    const int h  = bh & 127;
    const float* src = (h < 64) ? qkvbuf : aggbuf;
    const int    hh  = (h < 64) ? h : h - 64;
    const float* base = src + ((size_t)b * TD3 + (size_t)hh * 24) * HW;
    const float* qp = base;
    const float* kp = base + (size_t)8 * HW;
    const float* vp = base + (size_t)16 * HW;

    __shared__ float s_vk[72];
    const int tid = threadIdx.x;
    if (tid < 72) s_vk[tid] = 0.f;
    __syncthreads();

    float acc[72];
#pragma unroll
    for (int i = 0; i < 72; i++) acc[i] = 0.f;

    for (int n = tid; n < HW; n += 256) {
        float kv[8], vv[8];
#pragma unroll
        for (int e = 0; e < 8; e++) kv[e] = fmaxf(kp[(size_t)e * HW + n], 0.f);
#pragma unroll
        for (int d = 0; d < 8; d++) vv[d] = vp[(size_t)d * HW + n];
#pragma unroll
        for (int d = 0; d < 8; d++)
#pragma unroll
            for (int e = 0; e < 8; e++)
                acc[d * 8 + e] += vv[d] * kv[e];
#pragma unroll
        for (int e = 0; e < 8; e++) acc[64 + e] += kv[e];
    }

#pragma unroll
    for (int i = 0; i < 72; i++) {
        float v = acc[i];
        v += __shfl_down_sync(0xFFFFFFFFu, v, 16);
        v += __shfl_down_sync(0xFFFFFFFFu, v, 8);
        v += __shfl_down_sync(0xFFFFFFFFu, v, 4);
        v += __shfl_down_sync(0xFFFFFFFFu, v, 2);
        v += __shfl_down_sync(0xFFFFFFFFu, v, 1);
        if ((tid & 31) == 0) atomicAdd(&s_vk[i], v);
    }
    __syncthreads();

    float vk[72];
#pragma unroll
    for (int i = 0; i < 72; i++) vk[i] = s_vk[i];

    float* outp = att + ((size_t)b * 1024 + (size_t)h * 8) * HW;
    for (int n = tid; n < HW; n += 256) {
        float qv[8];
#pragma unroll
        for (int e = 0; e < 8; e++) qv[e] = fmaxf(qp[(size_t)e * HW + n], 0.f);
        float den = 0.f;
#pragma unroll
        for (int e = 0; e < 8; e++) den += vk[64 + e] * qv[e];
        float invd = 1.0f / (den + 1e-15f);
#pragma unroll
        for (int d = 0; d < 8; d++) {
            float o = 0.f;
#pragma unroll
            for (int e = 0; e < 8; e++) o += vk[d * 8 + e] * qv[e];
            outp[(size_t)d * HW + n] = o * invd;
        }
    }
}

// ---------------------------------------------------------------------------
extern "C" void kernel_launch(void* const* d_in, const int* in_sizes, int n_in,
                              void* d_out, int out_size)
{
    // Bind inputs by unique element counts (robust to ordering), with
    // positional fallback per metadata order: x, w_qkv, w_dw, w_pw, w_proj.
    const float *x = nullptr, *w_qkv = nullptr, *w_dw = nullptr,
                *w_pw = nullptr, *w_proj = nullptr;
    for (int i = 0; i < n_in; i++) {
        switch (in_sizes[i]) {
            case 8388608: x      = (const float*)d_in[i]; break; // 4*512*64*64
            case 786432:  w_qkv  = (const float*)d_in[i]; break; // 1536*512
            case 38400:   w_dw   = (const float*)d_in[i]; break; // 1536*25
            case 12288:   w_pw   = (const float*)d_in[i]; break; // 1536*8
            case 524288:  w_proj = (const float*)d_in[i]; break; // 512*1024
            default: break;
        }
    }
    if (!x || !w_qkv || !w_dw || !w_pw || !w_proj) {
        x      = (const float*)d_in[0];
        w_qkv  = (const float*)d_in[1];
        w_dw   = (const float*)d_in[2];
        w_pw   = (const float*)d_in[3];
        w_proj = (const float*)d_in[4];
    }
    float* out = (float*)d_out;

    float *qkv, *agg, *att;
    cudaGetSymbolAddress((void**)&qkv, g_qkv);
    cudaGetSymbolAddress((void**)&agg, g_agg);
    cudaGetSymbolAddress((void**)&att, g_att);

    // 1) qkv = w_qkv @ x        : M=1536, N=4096, K=512, batch 4
    sgemm_kernel<<<dim3(HW / 128, TD3 / 128, BATCH), 256>>>(
        w_qkv, x, qkv, nullptr, TD3, HW, 512);

    // 2) agg = grouped_pw(dw5x5(qkv))
    dwpw_kernel<<<dim3(4, 4, BATCH * 192), dim3(16, 16)>>>(qkv, w_dw, w_pw, agg);

    // 3) linear attention -> att (B,1024,HW)
    attn_kernel<<<BATCH * HEADS, 256>>>(qkv, agg, att);

    // 4) out = x + w_proj @ att : M=512, N=4096, K=1024, batch 4
    sgemm_kernel<<<dim3(HW / 128, 512 / 128, BATCH), 256>>>(
        w_proj, att, out, x, 512, HW, 1024);
}

// round 11
// speedup vs baseline: 1.6972x; 1.6972x over previous
#include <cuda_runtime.h>
#include <cuda_bf16.h>
#include <cstdint>

// ---------------------------------------------------------------------------
// DCAELiteMLA on GB300: mma.sync bf16 3-term-split GEMMs + fused dw/pw + attn.
// (tcgen05 is unavailable: harness device pass targets plain sm_103, which
//  rejects arch-'a' features. mma.sync/ldmatrix are sm_80+ and compile fine.)
// B=4, C=512, H=W=64 (HW=4096), td=512, DIM=8, heads=128, GROUPS_PW=192.
// ---------------------------------------------------------------------------

#define BATCH 4
#define HW    4096
#define TD3   1536
#define HEADS 128

// Scratch (__device__ globals; no allocation allowed)
__device__ float g_qkv[(size_t)BATCH * TD3 * HW];            // 96 MB
__device__ float g_agg[(size_t)BATCH * TD3 * HW];            // 96 MB
__device__ float g_att[(size_t)BATCH * 1024 * HW];           // 64 MB
__device__ __nv_bfloat16 g_xT3  [(size_t)BATCH * HW * 1536]; // 50 MB  [b][n][3*512]
__device__ __nv_bfloat16 g_attT3[(size_t)BATCH * HW * 3072]; // 100 MB [b][n][3*1024]
__device__ __nv_bfloat16 g_wqkv3 [(size_t)1536 * 1536];      // [m][3*512]
__device__ __nv_bfloat16 g_wproj3[(size_t)512 * 3072];       // [m][3*1024]

// ------------------------------- PTX helpers -------------------------------
__device__ __forceinline__ uint32_t smem_u32(const void* p) {
    uint32_t a;
    asm("{ .reg .u64 t; cvta.to.shared.u64 t, %1; cvt.u32.u64 %0, t; }"
        : "=r"(a) : "l"(p));
    return a;
}
#define CP_ASYNC16(saddr, gptr) \
    asm volatile("cp.async.cg.shared.global [%0], [%1], 16;" \
                 :: "r"((uint32_t)(saddr)), "l"(gptr) : "memory")
#define CP_ASYNC_COMMIT() asm volatile("cp.async.commit_group;" ::: "memory")
#define CP_ASYNC_WAIT0()  asm volatile("cp.async.wait_group 0;" ::: "memory")
#define SW128(off) ((off) ^ (((off) >> 3) & 0x70))

__device__ __forceinline__ void ldsm4(uint32_t& r0, uint32_t& r1, uint32_t& r2,
                                      uint32_t& r3, uint32_t addr) {
    asm volatile("ldmatrix.sync.aligned.m8n8.x4.shared.b16 {%0,%1,%2,%3}, [%4];"
                 : "=r"(r0), "=r"(r1), "=r"(r2), "=r"(r3) : "r"(addr));
}
__device__ __forceinline__ void mma16816(float* c, const uint32_t* a,
                                         uint32_t b0, uint32_t b1) {
    asm volatile("mma.sync.aligned.m16n8k16.row.col.f32.bf16.bf16.f32 "
                 "{%0,%1,%2,%3}, {%4,%5,%6,%7}, {%8,%9}, {%0,%1,%2,%3};"
                 : "+f"(c[0]), "+f"(c[1]), "+f"(c[2]), "+f"(c[3])
                 : "r"(a[0]), "r"(a[1]), "r"(a[2]), "r"(a[3]), "r"(b0), "r"(b1));
}

// ---------------------------------------------------------------------------
// mma.sync GEMM: C[b](MxN,f32,row-major) = A3(M x K3 bf16, K-major, shared
// over batch) @ B3T[b]^T (B3T: N rows x K3 bf16, K-major)  [+ R[b]].
// CTA tile 128x128, K-chunk 64 (one SW128 128B row), cp.async double buffer,
// 256 threads = 8 warps in 2(m) x 4(n) grid, warp tile 64x32.
// ---------------------------------------------------------------------------
#define GEMM_SMEM_BYTES (4 * 16384 + 1024)
__global__ __launch_bounds__(256)
void mma_gemm(const __nv_bfloat16* __restrict__ A3,
              const __nv_bfloat16* __restrict__ B3T,
              float* __restrict__ C, const float* __restrict__ R,
              int M, int N, int K3)
{
    extern __shared__ char dsm_raw[];
    const uint32_t smem = (smem_u32(dsm_raw) + 1023u) & ~1023u;

    const int tid  = threadIdx.x;
    const int wid  = tid >> 5;
    const int lane = tid & 31;
    const int nk   = K3 >> 6;

    const __nv_bfloat16* Abase = A3 + (size_t)blockIdx.y * 128 * K3;
    const __nv_bfloat16* Bbase = B3T + ((size_t)blockIdx.z * N
                               + (size_t)blockIdx.x * 128) * K3;

    // cp.async mapping: 2048 16B units per chunk (A 1024 + B 1024), 8/thread
    const int ur = tid >> 3;      // 0..31
    const int uu = tid & 7;       // 16B unit within 128B row

    auto prefetch = [&](int kc, int buf) {
        const uint32_t sa = smem + (uint32_t)buf * 32768u;
        const uint32_t sb = sa + 16384u;
        const __nv_bfloat16* ga = Abase + (size_t)kc * 64;
        const __nv_bfloat16* gb = Bbase + (size_t)kc * 64;
#pragma unroll
        for (int i = 0; i < 4; i++) {
            const int row = i * 32 + ur;
            const uint32_t sw = SW128((uint32_t)row * 128u + (uint32_t)uu * 16u);
            CP_ASYNC16(sa + sw, ga + (size_t)row * K3 + uu * 8);
            CP_ASYNC16(sb + sw, gb + (size_t)row * K3 + uu * 8);
        }
        CP_ASYNC_COMMIT();
    };

    float acc[4][4][4];
#pragma unroll
    for (int i = 0; i < 4; i++)
#pragma unroll
        for (int j = 0; j < 4; j++)
#pragma unroll
            for (int t = 0; t < 4; t++) acc[i][j][t] = 0.f;

    const int wm = wid >> 2;          // 0..1
    const int wn = wid & 3;           // 0..3
    const int mbase = wm * 64;
    const int nbase = wn * 32;
    const int sel = lane >> 3;        // ldmatrix matrix index
    const int l7  = lane & 7;

    prefetch(0, 0);

    for (int kc = 0; kc < nk; kc++) {
        CP_ASYNC_WAIT0();
        __syncthreads();
        if (kc + 1 < nk) prefetch(kc + 1, (kc & 1) ^ 1);

        const uint32_t sa = smem + (uint32_t)(kc & 1) * 32768u;
        const uint32_t sb = sa + 16384u;

#pragma unroll
        for (int ks = 0; ks < 4; ks++) {            // 4 x k16 per 64-chunk
            uint32_t af[4][4], bfr[2][4];
#pragma unroll
            for (int i = 0; i < 4; i++) {
                // A 16x16 tile: matrices {m0-7 k0-7, m8-15 k0-7, m0-7 k8-15, m8-15 k8-15}
                const int row = mbase + i * 16 + (sel & 1) * 8 + l7;
                const uint32_t kb = (uint32_t)ks * 32u + (uint32_t)(sel >> 1) * 16u;
                ldsm4(af[i][0], af[i][1], af[i][2], af[i][3],
                      sa + SW128((uint32_t)row * 128u + kb));
            }
#pragma unroll
            for (int j = 0; j < 2; j++) {
                // B pair of n8 tiles: {b0(2j), b1(2j), b0(2j+1), b1(2j+1)}
                const int row = nbase + j * 16 + (sel >> 1) * 8 + l7;
                const uint32_t kb = (uint32_t)ks * 32u + (uint32_t)(sel & 1) * 16u;
                ldsm4(bfr[j][0], bfr[j][1], bfr[j][2], bfr[j][3],
                      sb + SW128((uint32_t)row * 128u + kb));
            }
#pragma unroll
            for (int i = 0; i < 4; i++)
#pragma unroll
                for (int jj = 0; jj < 4; jj++)
                    mma16816(acc[i][jj], af[i],
                             bfr[jj >> 1][(jj & 1) * 2],
                             bfr[jj >> 1][(jj & 1) * 2 + 1]);
        }
    }

    // Epilogue: c0,c1 = C[g][2t,2t+1]; c2,c3 = C[g+8][2t,2t+1]
    const int g   = lane >> 2;
    const int tig = lane & 3;
    const size_t cbz = (size_t)blockIdx.z * M;
#pragma unroll
    for (int i = 0; i < 4; i++) {
#pragma unroll
        for (int jj = 0; jj < 4; jj++) {
            const int row0 = blockIdx.y * 128 + mbase + i * 16 + g;
            const int col  = blockIdx.x * 128 + nbase + jj * 8 + 2 * tig;
            float* p0 = C + (cbz + row0) * N + col;
            float* p1 = C + (cbz + row0 + 8) * N + col;
            float2 v0 = make_float2(acc[i][jj][0], acc[i][jj][1]);
            float2 v1 = make_float2(acc[i][jj][2], acc[i][jj][3]);
            if (R) {
                const float2 r0 = *(const float2*)(R + (cbz + row0) * N + col);
                const float2 r1 = *(const float2*)(R + (cbz + row0 + 8) * N + col);
                v0.x += r0.x; v0.y += r0.y;
                v1.x += r1.x; v1.y += r1.y;
            }
            *(float2*)p0 = v0;
            *(float2*)p1 = v1;
        }
    }
}

// ---------------------------------------------------------------------------
// A-side weight split: in [M][K] f32 -> out [M][3K] bf16 as [hi | lo | hi]
// ---------------------------------------------------------------------------
__global__ void w3_kernel(const float* __restrict__ in, __nv_bfloat16* __restrict__ out,
                          int K, int total)
{
    int idx = blockIdx.x * blockDim.x + threadIdx.x;
    if (idx >= total) return;
    int m = idx / K, k = idx - m * K;
    float v = in[idx];
    __nv_bfloat16 hi = __float2bfloat16(v);
    __nv_bfloat16 lo = __float2bfloat16(v - __bfloat162float(hi));
    __nv_bfloat16* o = out + (size_t)m * 3 * K;
    o[k] = hi; o[K + k] = lo; o[2 * K + k] = hi;
}

// ---------------------------------------------------------------------------
// B-side transpose+split: in [b][C][HW] f32 -> out [b][HW][3C] bf16 [hi|hi|lo]
// ---------------------------------------------------------------------------
__global__ void transpose_split(const float* __restrict__ in,
                                __nv_bfloat16* __restrict__ out, int C)
{
    __shared__ float t[32][33];
    const int bz = blockIdx.z;
    const float* inb = in + (size_t)bz * C * HW;
    __nv_bfloat16* ob = out + (size_t)bz * HW * 3 * C;
    const int tx = threadIdx.x, ty = threadIdx.y;
    const int k0 = blockIdx.y * 32, n0 = blockIdx.x * 32;
#pragma unroll
    for (int i = 0; i < 4; i++)
        t[ty + i * 8][tx] = inb[(size_t)(k0 + ty + i * 8) * HW + n0 + tx];
    __syncthreads();
    const int k = k0 + tx;
#pragma unroll
    for (int i = 0; i < 4; i++) {
        const int n = n0 + ty + i * 8;
        float v = t[tx][ty + i * 8];
        __nv_bfloat16 hi = __float2bfloat16(v);
        __nv_bfloat16 lo = __float2bfloat16(v - __bfloat162float(hi));
        __nv_bfloat16* o = ob + (size_t)n * 3 * C;
        o[k] = hi; o[C + k] = hi; o[2 * C + k] = lo;
    }
}

// ---------------------------------------------------------------------------
// Fused depthwise 5x5 (pad=2) + grouped 1x1 (192 groups, 8->8). Unchanged.
// ---------------------------------------------------------------------------
__global__ __launch_bounds__(256)
void dwpw_kernel(const float* __restrict__ qkv, const float* __restrict__ wdw,
                 const float* __restrict__ wpw, float* __restrict__ agg)
{
    __shared__ float s_in[8][20][20];
    __shared__ float s_wdw[8][25];
    __shared__ float s_wpw[8][8];

    const int tid = threadIdx.y * 16 + threadIdx.x;
    const int bz  = blockIdx.z;
    const int b   = bz / 192;
    const int g   = bz - b * 192;
    const int x0  = blockIdx.x * 16;
    const int y0  = blockIdx.y * 16;

    const float* inb = qkv + ((size_t)b * TD3 + (size_t)g * 8) * HW;

    for (int i = tid; i < 8 * 25; i += 256)
        s_wdw[i / 25][i % 25] = wdw[(g * 8 + i / 25) * 25 + (i % 25)];
    if (tid < 64)
        s_wpw[tid >> 3][tid & 7] = wpw[(g * 8 + (tid >> 3)) * 8 + (tid & 7)];

    for (int idx = tid; idx < 8 * 400; idx += 256) {
        int c  = idx / 400;
        int p  = idx - c * 400;
        int iy = p / 20;
        int ix = p - iy * 20;
        int gy = y0 + iy - 2;
        int gx = x0 + ix - 2;
        float v = 0.f;
        if (gy >= 0 && gy < 64 && gx >= 0 && gx < 64)
            v = inb[(size_t)c * HW + gy * 64 + gx];
        s_in[c][iy][ix] = v;
    }
    __syncthreads();

    const int txx = threadIdx.x, tyy = threadIdx.y;
    float dw[8];
#pragma unroll
    for (int c = 0; c < 8; c++) {
        float s = 0.f;
#pragma unroll
        for (int dy = 0; dy < 5; dy++)
#pragma unroll
            for (int dx = 0; dx < 5; dx++)
                s += s_wdw[c][dy * 5 + dx] * s_in[c][tyy + dy][txx + dx];
        dw[c] = s;
    }

    float* outb = agg + ((size_t)b * TD3 + (size_t)g * 8) * HW
                      + (y0 + tyy) * 64 + (x0 + txx);
#pragma unroll
    for (int o = 0; o < 8; o++) {
        float s = 0.f;
#pragma unroll
        for (int i = 0; i < 8; i++) s += s_wpw[o][i] * dw[i];
        outb[(size_t)o * HW] = s;
    }
}

// ---------------------------------------------------------------------------
// Linear attention per (b, head). Unchanged.
// ---------------------------------------------------------------------------
__global__ __launch_bounds__(256)
void attn_kernel(const float* __restrict__ qkvbuf, const float* __restrict__ aggbuf,
                 float* __restrict__ att)
{
    const int bh = blockIdx.x;
    const int b  = bh >> 7;
    const int h  = bh & 127;
    const float* src = (h < 64) ? qkvbuf : aggbuf;
    const int    hh  = (h < 64) ? h : h - 64;
    const float* base = src + ((size_t)b * TD3 + (size_t)hh * 24) * HW;
    const float* qp = base;
    const float* kp = base + (size_t)8 * HW;
    const float* vp = base + (size_t)16 * HW;

    __shared__ float s_vk[72];
    const int tid = threadIdx.x;
    if (tid < 72) s_vk[tid] = 0.f;
    __syncthreads();

    float acc[72];
#pragma unroll
    for (int i = 0; i < 72; i++) acc[i] = 0.f;

    for (int n = tid; n < HW; n += 256) {
        float kv[8], vv[8];
#pragma unroll
        for (int e = 0; e < 8; e++) kv[e] = fmaxf(kp[(size_t)e * HW + n], 0.f);
#pragma unroll
        for (int d = 0; d < 8; d++) vv[d] = vp[(size_t)d * HW + n];
#pragma unroll
        for (int d = 0; d < 8; d++)
#pragma unroll
            for (int e = 0; e < 8; e++)
                acc[d * 8 + e] += vv[d] * kv[e];
#pragma unroll
        for (int e = 0; e < 8; e++) acc[64 + e] += kv[e];
    }

#pragma unroll
    for (int i = 0; i < 72; i++) {
        float v = acc[i];
        v += __shfl_down_sync(0xFFFFFFFFu, v, 16);
        v += __shfl_down_sync(0xFFFFFFFFu, v, 8);
        v += __shfl_down_sync(0xFFFFFFFFu, v, 4);
        v += __shfl_down_sync(0xFFFFFFFFu, v, 2);
        v += __shfl_down_sync(0xFFFFFFFFu, v, 1);
        if ((tid & 31) == 0) atomicAdd(&s_vk[i], v);
    }
    __syncthreads();

    float vk[72];
#pragma unroll
    for (int i = 0; i < 72; i++) vk[i] = s_vk[i];

    float* outp = att + ((size_t)b * 1024 + (size_t)h * 8) * HW;
    for (int n = tid; n < HW; n += 256) {
        float qv[8];
#pragma unroll
        for (int e = 0; e < 8; e++) qv[e] = fmaxf(qp[(size_t)e * HW + n], 0.f);
        float den = 0.f;
#pragma unroll
        for (int e = 0; e < 8; e++) den += vk[64 + e] * qv[e];
        float invd = 1.0f / (den + 1e-15f);
#pragma unroll
        for (int d = 0; d < 8; d++) {
            float o = 0.f;
#pragma unroll
            for (int e = 0; e < 8; e++) o += vk[d * 8 + e] * qv[e];
            outp[(size_t)d * HW + n] = o * invd;
        }
    }
}

// ---------------------------------------------------------------------------
extern "C" void kernel_launch(void* const* d_in, const int* in_sizes, int n_in,
                              void* d_out, int out_size)
{
    const float *x = nullptr, *w_qkv = nullptr, *w_dw = nullptr,
                *w_pw = nullptr, *w_proj = nullptr;
    for (int i = 0; i < n_in; i++) {
        switch (in_sizes[i]) {
            case 8388608: x      = (const float*)d_in[i]; break;
            case 786432:  w_qkv  = (const float*)d_in[i]; break;
            case 38400:   w_dw   = (const float*)d_in[i]; break;
            case 12288:   w_pw   = (const float*)d_in[i]; break;
            case 524288:  w_proj = (const float*)d_in[i]; break;
            default: break;
        }
    }
    if (!x || !w_qkv || !w_dw || !w_pw || !w_proj) {
        x      = (const float*)d_in[0];
        w_qkv  = (const float*)d_in[1];
        w_dw   = (const float*)d_in[2];
        w_pw   = (const float*)d_in[3];
        w_proj = (const float*)d_in[4];
    }
    float* out = (float*)d_out;

    float *qkv, *agg, *att;
    __nv_bfloat16 *xT3, *attT3, *wqkv3, *wproj3;
    cudaGetSymbolAddress((void**)&qkv,    g_qkv);
    cudaGetSymbolAddress((void**)&agg,    g_agg);
    cudaGetSymbolAddress((void**)&att,    g_att);
    cudaGetSymbolAddress((void**)&xT3,    g_xT3);
    cudaGetSymbolAddress((void**)&attT3,  g_attT3);
    cudaGetSymbolAddress((void**)&wqkv3,  g_wqkv3);
    cudaGetSymbolAddress((void**)&wproj3, g_wproj3);

    cudaFuncSetAttribute(mma_gemm, cudaFuncAttributeMaxDynamicSharedMemorySize,
                         GEMM_SMEM_BYTES);

    // Operand prep (bf16 hi/lo splits)
    w3_kernel<<<(1536 * 512 + 255) / 256, 256>>>(w_qkv, wqkv3, 512, 1536 * 512);
    w3_kernel<<<(512 * 1024 + 255) / 256, 256>>>(w_proj, wproj3, 1024, 512 * 1024);
    transpose_split<<<dim3(HW / 32, 512 / 32, BATCH), dim3(32, 8)>>>(x, xT3, 512);

    // 1) qkv = w_qkv @ x  : M=1536, N=4096, K3=1536
    mma_gemm<<<dim3(HW / 128, TD3 / 128, BATCH), 256, GEMM_SMEM_BYTES>>>(
        wqkv3, xT3, qkv, nullptr, TD3, HW, 1536);

    // 2) agg = grouped_pw(dw5x5(qkv))
    dwpw_kernel<<<dim3(4, 4, BATCH * 192), dim3(16, 16)>>>(qkv, w_dw, w_pw, agg);

    // 3) linear attention -> att (B,1024,HW)
    attn_kernel<<<BATCH * HEADS, 256>>>(qkv, agg, att);

    // prep att operand
    transpose_split<<<dim3(HW / 32, 1024 / 32, BATCH), dim3(32, 8)>>>(att, attT3, 1024);

    // 4) out = x + w_proj @ att : M=512, N=4096, K3=3072
    mma_gemm<<<dim3(HW / 128, 512 / 128, BATCH), 256, GEMM_SMEM_BYTES>>>(
        wproj3, attT3, out, x, 512, HW, 3072);
}

// round 13
// speedup vs baseline: 1.7935x; 1.0567x over previous
#include <cuda_runtime.h>
#include <cuda_bf16.h>
#include <cstdint>

// ---------------------------------------------------------------------------
// DCAELiteMLA on GB300: mma.sync bf16 3-term-split GEMMs + fused dw/pw + attn.
// GEMM: K-chunk 128 (two 64-K SW128 sub-tiles), 3-stage cp.async pipeline.
// B=4, C=512, H=W=64 (HW=4096), td=512, DIM=8, heads=128, GROUPS_PW=192.
// ---------------------------------------------------------------------------

#define BATCH 4
#define HW    4096
#define TD3   1536
#define HEADS 128

// Scratch (__device__ globals; no allocation allowed)
__device__ float g_qkv[(size_t)BATCH * TD3 * HW];            // 96 MB
__device__ float g_agg[(size_t)BATCH * TD3 * HW];            // 96 MB
__device__ float g_att[(size_t)BATCH * 1024 * HW];           // 64 MB
__device__ __nv_bfloat16 g_xT3  [(size_t)BATCH * HW * 1536]; // 50 MB  [b][n][3*512]
__device__ __nv_bfloat16 g_attT3[(size_t)BATCH * HW * 3072]; // 100 MB [b][n][3*1024]
__device__ __nv_bfloat16 g_wqkv3 [(size_t)1536 * 1536];      // [m][3*512]
__device__ __nv_bfloat16 g_wproj3[(size_t)512 * 3072];       // [m][3*1024]

// ------------------------------- PTX helpers -------------------------------
__device__ __forceinline__ uint32_t smem_u32(const void* p) {
    uint32_t a;
    asm("{ .reg .u64 t; cvta.to.shared.u64 t, %1; cvt.u32.u64 %0, t; }"
        : "=r"(a) : "l"(p));
    return a;
}
#define CP_ASYNC16(saddr, gptr) \
    asm volatile("cp.async.cg.shared.global [%0], [%1], 16;" \
                 :: "r"((uint32_t)(saddr)), "l"(gptr) : "memory")
#define CP_ASYNC_COMMIT() asm volatile("cp.async.commit_group;" ::: "memory")
#define CP_ASYNC_WAIT0()  asm volatile("cp.async.wait_group 0;" ::: "memory")
#define CP_ASYNC_WAIT1()  asm volatile("cp.async.wait_group 1;" ::: "memory")
#define SW128(off) ((off) ^ (((off) >> 3) & 0x70))

__device__ __forceinline__ void ldsm4(uint32_t& r0, uint32_t& r1, uint32_t& r2,
                                      uint32_t& r3, uint32_t addr) {
    asm volatile("ldmatrix.sync.aligned.m8n8.x4.shared.b16 {%0,%1,%2,%3}, [%4];"
                 : "=r"(r0), "=r"(r1), "=r"(r2), "=r"(r3) : "r"(addr));
}
__device__ __forceinline__ void mma16816(float* c, const uint32_t* a,
                                         uint32_t b0, uint32_t b1) {
    asm volatile("mma.sync.aligned.m16n8k16.row.col.f32.bf16.bf16.f32 "
                 "{%0,%1,%2,%3}, {%4,%5,%6,%7}, {%8,%9}, {%0,%1,%2,%3};"
                 : "+f"(c[0]), "+f"(c[1]), "+f"(c[2]), "+f"(c[3])
                 : "r"(a[0]), "r"(a[1]), "r"(a[2]), "r"(a[3]), "r"(b0), "r"(b1));
}

// ---------------------------------------------------------------------------
// mma.sync GEMM: C[b](MxN,f32,row-major) = A3(M x K3 bf16, K-major, shared
// over batch) @ B3T[b]^T (B3T: N rows x K3 bf16, K-major)  [+ R[b]].
// CTA tile 128x128. K-chunk 128 stored as two 64-K sub-tiles (16KB each) so
// SW128/ldmatrix addressing is identical to the validated 64-chunk version.
// 3 pipeline stages x 64KB, cp.async wait_group 1. 256 thr, 8 warps 2x4,
// warp tile 64x32.
// ---------------------------------------------------------------------------
#define STAGE_BYTES 65536
#define GEMM_SMEM_BYTES (3 * STAGE_BYTES + 1024)
__global__ __launch_bounds__(256)
void mma_gemm(const __nv_bfloat16* __restrict__ A3,
              const __nv_bfloat16* __restrict__ B3T,
              float* __restrict__ C, const float* __restrict__ R,
              int M, int N, int K3)
{
    extern __shared__ char dsm_raw[];
    const uint32_t smem = (smem_u32(dsm_raw) + 1023u) & ~1023u;

    const int tid  = threadIdx.x;
    const int wid  = tid >> 5;
    const int lane = tid & 31;
    const int nk   = K3 >> 7;          // 128-K chunks (12 or 24)

    const __nv_bfloat16* Abase = A3 + (size_t)blockIdx.y * 128 * K3;
    const __nv_bfloat16* Bbase = B3T + ((size_t)blockIdx.z * N
                               + (size_t)blockIdx.x * 128) * K3;

    const int ur = tid >> 3;      // 0..31 row group
    const int uu = tid & 7;       // 16B unit within 128B sub-tile row

    // prefetch chunk kc (128 K-elems) into stage st.
    // Stage layout: A sub0 | A sub1 | B sub0 | B sub1  (16KB each).
    auto prefetch = [&](int kc, int st) {
        const uint32_t sa = smem + (uint32_t)st * STAGE_BYTES;
        const __nv_bfloat16* ga = Abase + (size_t)kc * 128;
        const __nv_bfloat16* gb = Bbase + (size_t)kc * 128;
#pragma unroll
        for (int i = 0; i < 4; i++) {
            const int row = i * 32 + ur;
            const uint32_t sw = SW128((uint32_t)row * 128u + (uint32_t)uu * 16u);
#pragma unroll
            for (int j = 0; j < 2; j++) {
                CP_ASYNC16(sa + (uint32_t)j * 16384u + sw,
                           ga + (size_t)row * K3 + j * 64 + uu * 8);
                CP_ASYNC16(sa + 32768u + (uint32_t)j * 16384u + sw,
                           gb + (size_t)row * K3 + j * 64 + uu * 8);
            }
        }
        CP_ASYNC_COMMIT();
    };

    float acc[4][4][4];
#pragma unroll
    for (int i = 0; i < 4; i++)
#pragma unroll
        for (int j = 0; j < 4; j++)
#pragma unroll
            for (int t = 0; t < 4; t++) acc[i][j][t] = 0.f;

    const int wm = wid >> 2;          // 0..1
    const int wn = wid & 3;           // 0..3
    const int mbase = wm * 64;
    const int nbase = wn * 32;
    const int sel = lane >> 3;        // ldmatrix matrix index
    const int l7  = lane & 7;

    prefetch(0, 0);
    prefetch(1, 1);

    for (int kc = 0; kc < nk; kc++) {
        if (kc + 1 < nk) { CP_ASYNC_WAIT1(); } else { CP_ASYNC_WAIT0(); }
        __syncthreads();
        if (kc + 2 < nk) prefetch(kc + 2, (kc + 2) % 3);

        const uint32_t stg = smem + (uint32_t)(kc % 3) * STAGE_BYTES;

#pragma unroll
        for (int ks = 0; ks < 8; ks++) {            // 8 x k16 per 128-chunk
            const uint32_t sa = stg + (uint32_t)(ks >> 2) * 16384u;
            const uint32_t sb = stg + 32768u + (uint32_t)(ks >> 2) * 16384u;
            const int ks2 = ks & 3;
            uint32_t af[4][4], bfr[2][4];
#pragma unroll
            for (int i = 0; i < 4; i++) {
                // A 16x16 tile: {m0-7 k0-7, m8-15 k0-7, m0-7 k8-15, m8-15 k8-15}
                const int row = mbase + i * 16 + (sel & 1) * 8 + l7;
                const uint32_t kb = (uint32_t)ks2 * 32u + (uint32_t)(sel >> 1) * 16u;
                ldsm4(af[i][0], af[i][1], af[i][2], af[i][3],
                      sa + SW128((uint32_t)row * 128u + kb));
            }
#pragma unroll
            for (int j = 0; j < 2; j++) {
                // B pair of n8 tiles: {b0(2j), b1(2j), b0(2j+1), b1(2j+1)}
                const int row = nbase + j * 16 + (sel >> 1) * 8 + l7;
                const uint32_t kb = (uint32_t)ks2 * 32u + (uint32_t)(sel & 1) * 16u;
                ldsm4(bfr[j][0], bfr[j][1], bfr[j][2], bfr[j][3],
                      sb + SW128((uint32_t)row * 128u + kb));
            }
#pragma unroll
            for (int i = 0; i < 4; i++)
#pragma unroll
                for (int jj = 0; jj < 4; jj++)
                    mma16816(acc[i][jj], af[i],
                             bfr[jj >> 1][(jj & 1) * 2],
                             bfr[jj >> 1][(jj & 1) * 2 + 1]);
        }
    }

    // Epilogue: c0,c1 = C[g][2t,2t+1]; c2,c3 = C[g+8][2t,2t+1]
    const int g   = lane >> 2;
    const int tig = lane & 3;
    const size_t cbz = (size_t)blockIdx.z * M;
#pragma unroll
    for (int i = 0; i < 4; i++) {
#pragma unroll
        for (int jj = 0; jj < 4; jj++) {
            const int row0 = blockIdx.y * 128 + mbase + i * 16 + g;
            const int col  = blockIdx.x * 128 + nbase + jj * 8 + 2 * tig;
            float* p0 = C + (cbz + row0) * N + col;
            float* p1 = C + (cbz + row0 + 8) * N + col;
            float2 v0 = make_float2(acc[i][jj][0], acc[i][jj][1]);
            float2 v1 = make_float2(acc[i][jj][2], acc[i][jj][3]);
            if (R) {
                const float2 r0 = *(const float2*)(R + (cbz + row0) * N + col);
                const float2 r1 = *(const float2*)(R + (cbz + row0 + 8) * N + col);
                v0.x += r0.x; v0.y += r0.y;
                v1.x += r1.x; v1.y += r1.y;
            }
            *(float2*)p0 = v0;
            *(float2*)p1 = v1;
        }
    }
}

// ---------------------------------------------------------------------------
// A-side weight split: in [M][K] f32 -> out [M][3K] bf16 as [hi | lo | hi]
// ---------------------------------------------------------------------------
__global__ void w3_kernel(const float* __restrict__ in, __nv_bfloat16* __restrict__ out,
                          int K, int total)
{
    int idx = blockIdx.x * blockDim.x + threadIdx.x;
    if (idx >= total) return;
    int m = idx / K, k = idx - m * K;
    float v = in[idx];
    __nv_bfloat16 hi = __float2bfloat16(v);
    __nv_bfloat16 lo = __float2bfloat16(v - __bfloat162float(hi));
    __nv_bfloat16* o = out + (size_t)m * 3 * K;
    o[k] = hi; o[K + k] = lo; o[2 * K + k] = hi;
}

// ---------------------------------------------------------------------------
// B-side transpose+split: in [b][C][HW] f32 -> out [b][HW][3C] bf16 [hi|hi|lo]
// ---------------------------------------------------------------------------
__global__ void transpose_split(const float* __restrict__ in,
                                __nv_bfloat16* __restrict__ out, int C)
{
    __shared__ float t[32][33];
    const int bz = blockIdx.z;
    const float* inb = in + (size_t)bz * C * HW;
    __nv_bfloat16* ob = out + (size_t)bz * HW * 3 * C;
    const int tx = threadIdx.x, ty = threadIdx.y;
    const int k0 = blockIdx.y * 32, n0 = blockIdx.x * 32;
#pragma unroll
    for (int i = 0; i < 4; i++)
        t[ty + i * 8][tx] = inb[(size_t)(k0 + ty + i * 8) * HW + n0 + tx];
    __syncthreads();
    const int k = k0 + tx;
#pragma unroll
    for (int i = 0; i < 4; i++) {
        const int n = n0 + ty + i * 8;
        float v = t[tx][ty + i * 8];
        __nv_bfloat16 hi = __float2bfloat16(v);
        __nv_bfloat16 lo = __float2bfloat16(v - __bfloat162float(hi));
        __nv_bfloat16* o = ob + (size_t)n * 3 * C;
        o[k] = hi; o[C + k] = hi; o[2 * C + k] = lo;
    }
}

// ---------------------------------------------------------------------------
// Fused depthwise 5x5 (pad=2) + grouped 1x1 (192 groups, 8->8). Unchanged.
// ---------------------------------------------------------------------------
__global__ __launch_bounds__(256)
void dwpw_kernel(const float* __restrict__ qkv, const float* __restrict__ wdw,
                 const float* __restrict__ wpw, float* __restrict__ agg)
{
    __shared__ float s_in[8][20][20];
    __shared__ float s_wdw[8][25];
    __shared__ float s_wpw[8][8];

    const int tid = threadIdx.y * 16 + threadIdx.x;
    const int bz  = blockIdx.z;
    const int b   = bz / 192;
    const int g   = bz - b * 192;
    const int x0  = blockIdx.x * 16;
    const int y0  = blockIdx.y * 16;

    const float* inb = qkv + ((size_t)b * TD3 + (size_t)g * 8) * HW;

    for (int i = tid; i < 8 * 25; i += 256)
        s_wdw[i / 25][i % 25] = wdw[(g * 8 + i / 25) * 25 + (i % 25)];
    if (tid < 64)
        s_wpw[tid >> 3][tid & 7] = wpw[(g * 8 + (tid >> 3)) * 8 + (tid & 7)];

    for (int idx = tid; idx < 8 * 400; idx += 256) {
        int c  = idx / 400;
        int p  = idx - c * 400;
        int iy = p / 20;
        int ix = p - iy * 20;
        int gy = y0 + iy - 2;
        int gx = x0 + ix - 2;
        float v = 0.f;
        if (gy >= 0 && gy < 64 && gx >= 0 && gx < 64)
            v = inb[(size_t)c * HW + gy * 64 + gx];
        s_in[c][iy][ix] = v;
    }
    __syncthreads();

    const int txx = threadIdx.x, tyy = threadIdx.y;
    float dw[8];
#pragma unroll
    for (int c = 0; c < 8; c++) {
        float s = 0.f;
#pragma unroll
        for (int dy = 0; dy < 5; dy++)
#pragma unroll
            for (int dx = 0; dx < 5; dx++)
                s += s_wdw[c][dy * 5 + dx] * s_in[c][tyy + dy][txx + dx];
        dw[c] = s;
    }

    float* outb = agg + ((size_t)b * TD3 + (size_t)g * 8) * HW
                      + (y0 + tyy) * 64 + (x0 + txx);
#pragma unroll
    for (int o = 0; o < 8; o++) {
        float s = 0.f;
#pragma unroll
        for (int i = 0; i < 8; i++) s += s_wpw[o][i] * dw[i];
        outb[(size_t)o * HW] = s;
    }
}

// ---------------------------------------------------------------------------
// Linear attention per (b, head). Unchanged.
// ---------------------------------------------------------------------------
__global__ __launch_bounds__(256)
void attn_kernel(const float* __restrict__ qkvbuf, const float* __restrict__ aggbuf,
                 float* __restrict__ att)
{
    const int bh = blockIdx.x;
    const int b  = bh >> 7;
    const int h  = bh & 127;
    const float* src = (h < 64) ? qkvbuf : aggbuf;
    const int    hh  = (h < 64) ? h : h - 64;
    const float* base = src + ((size_t)b * TD3 + (size_t)hh * 24) * HW;
    const float* qp = base;
    const float* kp = base + (size_t)8 * HW;
    const float* vp = base + (size_t)16 * HW;

    __shared__ float s_vk[72];
    const int tid = threadIdx.x;
    if (tid < 72) s_vk[tid] = 0.f;
    __syncthreads();

    float acc[72];
#pragma unroll
    for (int i = 0; i < 72; i++) acc[i] = 0.f;

    for (int n = tid; n < HW; n += 256) {
        float kv[8], vv[8];
#pragma unroll
        for (int e = 0; e < 8; e++) kv[e] = fmaxf(kp[(size_t)e * HW + n], 0.f);
#pragma unroll
        for (int d = 0; d < 8; d++) vv[d] = vp[(size_t)d * HW + n];
#pragma unroll
        for (int d = 0; d < 8; d++)
#pragma unroll
            for (int e = 0; e < 8; e++)
                acc[d * 8 + e] += vv[d] * kv[e];
#pragma unroll
        for (int e = 0; e < 8; e++) acc[64 + e] += kv[e];
    }

#pragma unroll
    for (int i = 0; i < 72; i++) {
        float v = acc[i];
        v += __shfl_down_sync(0xFFFFFFFFu, v, 16);
        v += __shfl_down_sync(0xFFFFFFFFu, v, 8);
        v += __shfl_down_sync(0xFFFFFFFFu, v, 4);
        v += __shfl_down_sync(0xFFFFFFFFu, v, 2);
        v += __shfl_down_sync(0xFFFFFFFFu, v, 1);
        if ((tid & 31) == 0) atomicAdd(&s_vk[i], v);
    }
    __syncthreads();

    float vk[72];
#pragma unroll
    for (int i = 0; i < 72; i++) vk[i] = s_vk[i];

    float* outp = att + ((size_t)b * 1024 + (size_t)h * 8) * HW;
    for (int n = tid; n < HW; n += 256) {
        float qv[8];
#pragma unroll
        for (int e = 0; e < 8; e++) qv[e] = fmaxf(qp[(size_t)e * HW + n], 0.f);
        float den = 0.f;
#pragma unroll
        for (int e = 0; e < 8; e++) den += vk[64 + e] * qv[e];
        float invd = 1.0f / (den + 1e-15f);
#pragma unroll
        for (int d = 0; d < 8; d++) {
            float o = 0.f;
#pragma unroll
            for (int e = 0; e < 8; e++) o += vk[d * 8 + e] * qv[e];
            outp[(size_t)d * HW + n] = o * invd;
        }
    }
}

// ---------------------------------------------------------------------------
extern "C" void kernel_launch(void* const* d_in, const int* in_sizes, int n_in,
                              void* d_out, int out_size)
{
    const float *x = nullptr, *w_qkv = nullptr, *w_dw = nullptr,
                *w_pw = nullptr, *w_proj = nullptr;
    for (int i = 0; i < n_in; i++) {
        switch (in_sizes[i]) {
            case 8388608: x      = (const float*)d_in[i]; break;
            case 786432:  w_qkv  = (const float*)d_in[i]; break;
            case 38400:   w_dw   = (const float*)d_in[i]; break;
            case 12288:   w_pw   = (const float*)d_in[i]; break;
            case 524288:  w_proj = (const float*)d_in[i]; break;
            default: break;
        }
    }
    if (!x || !w_qkv || !w_dw || !w_pw || !w_proj) {
        x      = (const float*)d_in[0];
        w_qkv  = (const float*)d_in[1];
        w_dw   = (const float*)d_in[2];
        w_pw   = (const float*)d_in[3];
        w_proj = (const float*)d_in[4];
    }
    float* out = (float*)d_out;

    float *qkv, *agg, *att;
    __nv_bfloat16 *xT3, *attT3, *wqkv3, *wproj3;
    cudaGetSymbolAddress((void**)&qkv,    g_qkv);
    cudaGetSymbolAddress((void**)&agg,    g_agg);
    cudaGetSymbolAddress((void**)&att,    g_att);
    cudaGetSymbolAddress((void**)&xT3,    g_xT3);
    cudaGetSymbolAddress((void**)&attT3,  g_attT3);
    cudaGetSymbolAddress((void**)&wqkv3,  g_wqkv3);
    cudaGetSymbolAddress((void**)&wproj3, g_wproj3);

    cudaFuncSetAttribute(mma_gemm, cudaFuncAttributeMaxDynamicSharedMemorySize,
                         GEMM_SMEM_BYTES);

    // Operand prep (bf16 hi/lo splits)
    w3_kernel<<<(1536 * 512 + 255) / 256, 256>>>(w_qkv, wqkv3, 512, 1536 * 512);
    w3_kernel<<<(512 * 1024 + 255) / 256, 256>>>(w_proj, wproj3, 1024, 512 * 1024);
    transpose_split<<<dim3(HW / 32, 512 / 32, BATCH), dim3(32, 8)>>>(x, xT3, 512);

    // 1) qkv = w_qkv @ x  : M=1536, N=4096, K3=1536
    mma_gemm<<<dim3(HW / 128, TD3 / 128, BATCH), 256, GEMM_SMEM_BYTES>>>(
        wqkv3, xT3, qkv, nullptr, TD3, HW, 1536);

    // 2) agg = grouped_pw(dw5x5(qkv))
    dwpw_kernel<<<dim3(4, 4, BATCH * 192), dim3(16, 16)>>>(qkv, w_dw, w_pw, agg);

    // 3) linear attention -> att (B,1024,HW)
    attn_kernel<<<BATCH * HEADS, 256>>>(qkv, agg, att);

    // prep att operand
    transpose_split<<<dim3(HW / 32, 1024 / 32, BATCH), dim3(32, 8)>>>(att, attT3, 1024);

    // 4) out = x + w_proj @ att : M=512, N=4096, K3=3072
    mma_gemm<<<dim3(HW / 128, 512 / 128, BATCH), 256, GEMM_SMEM_BYTES>>>(
        wproj3, attT3, out, x, 512, HW, 3072);
}

// round 14
// speedup vs baseline: 1.8712x; 1.0433x over previous
#include <cuda_runtime.h>
#include <cuda_bf16.h>
#include <cstdint>

// ---------------------------------------------------------------------------
// DCAELiteMLA on GB300: mma.sync bf16 3-term-split GEMMs + fused dw/pw + attn.
// GEMM: K-chunk 64, 3-stage cp.async pipeline, 2 CTAs/SM (launch_bounds 256,2).
// B=4, C=512, H=W=64 (HW=4096), td=512, DIM=8, heads=128, GROUPS_PW=192.
// ---------------------------------------------------------------------------

#define BATCH 4
#define HW    4096
#define TD3   1536
#define HEADS 128

// Scratch (__device__ globals; no allocation allowed)
__device__ float g_qkv[(size_t)BATCH * TD3 * HW];            // 96 MB
__device__ float g_agg[(size_t)BATCH * TD3 * HW];            // 96 MB
__device__ float g_att[(size_t)BATCH * 1024 * HW];           // 64 MB
__device__ __nv_bfloat16 g_xT3  [(size_t)BATCH * HW * 1536]; // 50 MB  [b][n][3*512]
__device__ __nv_bfloat16 g_attT3[(size_t)BATCH * HW * 3072]; // 100 MB [b][n][3*1024]
__device__ __nv_bfloat16 g_wqkv3 [(size_t)1536 * 1536];      // [m][3*512]
__device__ __nv_bfloat16 g_wproj3[(size_t)512 * 3072];       // [m][3*1024]

// ------------------------------- PTX helpers -------------------------------
__device__ __forceinline__ uint32_t smem_u32(const void* p) {
    uint32_t a;
    asm("{ .reg .u64 t; cvta.to.shared.u64 t, %1; cvt.u32.u64 %0, t; }"
        : "=r"(a) : "l"(p));
    return a;
}
#define CP_ASYNC16(saddr, gptr) \
    asm volatile("cp.async.cg.shared.global [%0], [%1], 16;" \
                 :: "r"((uint32_t)(saddr)), "l"(gptr) : "memory")
#define CP_ASYNC_COMMIT() asm volatile("cp.async.commit_group;" ::: "memory")
#define CP_ASYNC_WAIT0()  asm volatile("cp.async.wait_group 0;" ::: "memory")
#define CP_ASYNC_WAIT1()  asm volatile("cp.async.wait_group 1;" ::: "memory")
#define SW128(off) ((off) ^ (((off) >> 3) & 0x70))

__device__ __forceinline__ void ldsm4(uint32_t& r0, uint32_t& r1, uint32_t& r2,
                                      uint32_t& r3, uint32_t addr) {
    asm volatile("ldmatrix.sync.aligned.m8n8.x4.shared.b16 {%0,%1,%2,%3}, [%4];"
                 : "=r"(r0), "=r"(r1), "=r"(r2), "=r"(r3) : "r"(addr));
}
__device__ __forceinline__ void mma16816(float* c, const uint32_t* a,
                                         uint32_t b0, uint32_t b1) {
    asm volatile("mma.sync.aligned.m16n8k16.row.col.f32.bf16.bf16.f32 "
                 "{%0,%1,%2,%3}, {%4,%5,%6,%7}, {%8,%9}, {%0,%1,%2,%3};"
                 : "+f"(c[0]), "+f"(c[1]), "+f"(c[2]), "+f"(c[3])
                 : "r"(a[0]), "r"(a[1]), "r"(a[2]), "r"(a[3]), "r"(b0), "r"(b1));
}

// ---------------------------------------------------------------------------
// mma.sync GEMM: C[b](MxN,f32,row-major) = A3(M x K3 bf16, K-major, shared
// over batch) @ B3T[b]^T (B3T: N rows x K3 bf16, K-major)  [+ R[b]].
// CTA tile 128x128, K-chunk 64 (one SW128 atom), 3 stages x 32KB,
// cp.async wait_group 1, 256 thr = 8 warps 2x4, warp tile 64x32.
// launch_bounds(256,2): 2 CTAs/SM (regs<=128, smem 97KB -> 194KB/SM).
// ---------------------------------------------------------------------------
#define STAGE_BYTES 32768
#define GEMM_SMEM_BYTES (3 * STAGE_BYTES + 1024)
__global__ __launch_bounds__(256, 2)
void mma_gemm(const __nv_bfloat16* __restrict__ A3,
              const __nv_bfloat16* __restrict__ B3T,
              float* __restrict__ C, const float* __restrict__ R,
              int M, int N, int K3)
{
    extern __shared__ char dsm_raw[];
    const uint32_t smem = (smem_u32(dsm_raw) + 1023u) & ~1023u;

    const int tid  = threadIdx.x;
    const int wid  = tid >> 5;
    const int lane = tid & 31;
    const int nk   = K3 >> 6;          // 64-K chunks (24 or 48)

    const __nv_bfloat16* Abase = A3 + (size_t)blockIdx.y * 128 * K3;
    const __nv_bfloat16* Bbase = B3T + ((size_t)blockIdx.z * N
                               + (size_t)blockIdx.x * 128) * K3;

    const int ur = tid >> 3;      // 0..31 row group
    const int uu = tid & 7;       // 16B unit within 128B row

    // prefetch chunk kc (64 K-elems) into stage st: A 16KB | B 16KB
    auto prefetch = [&](int kc, int st) {
        const uint32_t sa = smem + (uint32_t)st * STAGE_BYTES;
        const uint32_t sb = sa + 16384u;
        const __nv_bfloat16* ga = Abase + (size_t)kc * 64;
        const __nv_bfloat16* gb = Bbase + (size_t)kc * 64;
#pragma unroll
        for (int i = 0; i < 4; i++) {
            const int row = i * 32 + ur;
            const uint32_t sw = SW128((uint32_t)row * 128u + (uint32_t)uu * 16u);
            CP_ASYNC16(sa + sw, ga + (size_t)row * K3 + uu * 8);
            CP_ASYNC16(sb + sw, gb + (size_t)row * K3 + uu * 8);
        }
        CP_ASYNC_COMMIT();
    };

    float acc[4][4][4];
#pragma unroll
    for (int i = 0; i < 4; i++)
#pragma unroll
        for (int j = 0; j < 4; j++)
#pragma unroll
            for (int t = 0; t < 4; t++) acc[i][j][t] = 0.f;

    const int wm = wid >> 2;          // 0..1
    const int wn = wid & 3;           // 0..3
    const int mbase = wm * 64;
    const int nbase = wn * 32;
    const int sel = lane >> 3;        // ldmatrix matrix index
    const int l7  = lane & 7;

    prefetch(0, 0);
    prefetch(1, 1);

    for (int kc = 0; kc < nk; kc++) {
        if (kc + 1 < nk) { CP_ASYNC_WAIT1(); } else { CP_ASYNC_WAIT0(); }
        __syncthreads();
        if (kc + 2 < nk) prefetch(kc + 2, (kc + 2) % 3);

        const uint32_t sa = smem + (uint32_t)(kc % 3) * STAGE_BYTES;
        const uint32_t sb = sa + 16384u;

#pragma unroll
        for (int ks = 0; ks < 4; ks++) {            // 4 x k16 per 64-chunk
            uint32_t af[4][4], bfr[2][4];
#pragma unroll
            for (int i = 0; i < 4; i++) {
                // A 16x16 tile: {m0-7 k0-7, m8-15 k0-7, m0-7 k8-15, m8-15 k8-15}
                const int row = mbase + i * 16 + (sel & 1) * 8 + l7;
                const uint32_t kb = (uint32_t)ks * 32u + (uint32_t)(sel >> 1) * 16u;
                ldsm4(af[i][0], af[i][1], af[i][2], af[i][3],
                      sa + SW128((uint32_t)row * 128u + kb));
            }
#pragma unroll
            for (int j = 0; j < 2; j++) {
                // B pair of n8 tiles: {b0(2j), b1(2j), b0(2j+1), b1(2j+1)}
                const int row = nbase + j * 16 + (sel >> 1) * 8 + l7;
                const uint32_t kb = (uint32_t)ks * 32u + (uint32_t)(sel & 1) * 16u;
                ldsm4(bfr[j][0], bfr[j][1], bfr[j][2], bfr[j][3],
                      sb + SW128((uint32_t)row * 128u + kb));
            }
#pragma unroll
            for (int i = 0; i < 4; i++)
#pragma unroll
                for (int jj = 0; jj < 4; jj++)
                    mma16816(acc[i][jj], af[i],
                             bfr[jj >> 1][(jj & 1) * 2],
                             bfr[jj >> 1][(jj & 1) * 2 + 1]);
        }
    }

    // Epilogue: c0,c1 = C[g][2t,2t+1]; c2,c3 = C[g+8][2t,2t+1]
    const int g   = lane >> 2;
    const int tig = lane & 3;
    const size_t cbz = (size_t)blockIdx.z * M;
#pragma unroll
    for (int i = 0; i < 4; i++) {
#pragma unroll
        for (int jj = 0; jj < 4; jj++) {
            const int row0 = blockIdx.y * 128 + mbase + i * 16 + g;
            const int col  = blockIdx.x * 128 + nbase + jj * 8 + 2 * tig;
            float* p0 = C + (cbz + row0) * N + col;
            float* p1 = C + (cbz + row0 + 8) * N + col;
            float2 v0 = make_float2(acc[i][jj][0], acc[i][jj][1]);
            float2 v1 = make_float2(acc[i][jj][2], acc[i][jj][3]);
            if (R) {
                const float2 r0 = *(const float2*)(R + (cbz + row0) * N + col);
                const float2 r1 = *(const float2*)(R + (cbz + row0 + 8) * N + col);
                v0.x += r0.x; v0.y += r0.y;
                v1.x += r1.x; v1.y += r1.y;
            }
            *(float2*)p0 = v0;
            *(float2*)p1 = v1;
        }
    }
}

// ---------------------------------------------------------------------------
// A-side weight split: in [M][K] f32 -> out [M][3K] bf16 as [hi | lo | hi]
// ---------------------------------------------------------------------------
__global__ void w3_kernel(const float* __restrict__ in, __nv_bfloat16* __restrict__ out,
                          int K, int total)
{
    int idx = blockIdx.x * blockDim.x + threadIdx.x;
    if (idx >= total) return;
    int m = idx / K, k = idx - m * K;
    float v = in[idx];
    __nv_bfloat16 hi = __float2bfloat16(v);
    __nv_bfloat16 lo = __float2bfloat16(v - __bfloat162float(hi));
    __nv_bfloat16* o = out + (size_t)m * 3 * K;
    o[k] = hi; o[K + k] = lo; o[2 * K + k] = hi;
}

// ---------------------------------------------------------------------------
// B-side transpose+split: in [b][C][HW] f32 -> out [b][HW][3C] bf16 [hi|hi|lo]
// ---------------------------------------------------------------------------
__global__ void transpose_split(const float* __restrict__ in,
                                __nv_bfloat16* __restrict__ out, int C)
{
    __shared__ float t[32][33];
    const int bz = blockIdx.z;
    const float* inb = in + (size_t)bz * C * HW;
    __nv_bfloat16* ob = out + (size_t)bz * HW * 3 * C;
    const int tx = threadIdx.x, ty = threadIdx.y;
    const int k0 = blockIdx.y * 32, n0 = blockIdx.x * 32;
#pragma unroll
    for (int i = 0; i < 4; i++)
        t[ty + i * 8][tx] = inb[(size_t)(k0 + ty + i * 8) * HW + n0 + tx];
    __syncthreads();
    const int k = k0 + tx;
#pragma unroll
    for (int i = 0; i < 4; i++) {
        const int n = n0 + ty + i * 8;
        float v = t[tx][ty + i * 8];
        __nv_bfloat16 hi = __float2bfloat16(v);
        __nv_bfloat16 lo = __float2bfloat16(v - __bfloat162float(hi));
        __nv_bfloat16* o = ob + (size_t)n * 3 * C;
        o[k] = hi; o[C + k] = hi; o[2 * C + k] = lo;
    }
}

// ---------------------------------------------------------------------------
// Fused depthwise 5x5 (pad=2) + grouped 1x1 (192 groups, 8->8). Unchanged.
// ---------------------------------------------------------------------------
__global__ __launch_bounds__(256)
void dwpw_kernel(const float* __restrict__ qkv, const float* __restrict__ wdw,
                 const float* __restrict__ wpw, float* __restrict__ agg)
{
    __shared__ float s_in[8][20][20];
    __shared__ float s_wdw[8][25];
    __shared__ float s_wpw[8][8];

    const int tid = threadIdx.y * 16 + threadIdx.x;
    const int bz  = blockIdx.z;
    const int b   = bz / 192;
    const int g   = bz - b * 192;
    const int x0  = blockIdx.x * 16;
    const int y0  = blockIdx.y * 16;

    const float* inb = qkv + ((size_t)b * TD3 + (size_t)g * 8) * HW;

    for (int i = tid; i < 8 * 25; i += 256)
        s_wdw[i / 25][i % 25] = wdw[(g * 8 + i / 25) * 25 + (i % 25)];
    if (tid < 64)
        s_wpw[tid >> 3][tid & 7] = wpw[(g * 8 + (tid >> 3)) * 8 + (tid & 7)];

    for (int idx = tid; idx < 8 * 400; idx += 256) {
        int c  = idx / 400;
        int p  = idx - c * 400;
        int iy = p / 20;
        int ix = p - iy * 20;
        int gy = y0 + iy - 2;
        int gx = x0 + ix - 2;
        float v = 0.f;
        if (gy >= 0 && gy < 64 && gx >= 0 && gx < 64)
            v = inb[(size_t)c * HW + gy * 64 + gx];
        s_in[c][iy][ix] = v;
    }
    __syncthreads();

    const int txx = threadIdx.x, tyy = threadIdx.y;
    float dw[8];
#pragma unroll
    for (int c = 0; c < 8; c++) {
        float s = 0.f;
#pragma unroll
        for (int dy = 0; dy < 5; dy++)
#pragma unroll
            for (int dx = 0; dx < 5; dx++)
                s += s_wdw[c][dy * 5 + dx] * s_in[c][tyy + dy][txx + dx];
        dw[c] = s;
    }

    float* outb = agg + ((size_t)b * TD3 + (size_t)g * 8) * HW
                      + (y0 + tyy) * 64 + (x0 + txx);
#pragma unroll
    for (int o = 0; o < 8; o++) {
        float s = 0.f;
#pragma unroll
        for (int i = 0; i < 8; i++) s += s_wpw[o][i] * dw[i];
        outb[(size_t)o * HW] = s;
    }
}

// ---------------------------------------------------------------------------
// Linear attention per (b, head). Unchanged.
// ---------------------------------------------------------------------------
__global__ __launch_bounds__(256)
void attn_kernel(const float* __restrict__ qkvbuf, const float* __restrict__ aggbuf,
                 float* __restrict__ att)
{
    const int bh = blockIdx.x;
    const int b  = bh >> 7;
    const int h  = bh & 127;
    const float* src = (h < 64) ? qkvbuf : aggbuf;
    const int    hh  = (h < 64) ? h : h - 64;
    const float* base = src + ((size_t)b * TD3 + (size_t)hh * 24) * HW;
    const float* qp = base;
    const float* kp = base + (size_t)8 * HW;
    const float* vp = base + (size_t)16 * HW;

    __shared__ float s_vk[72];
    const int tid = threadIdx.x;
    if (tid < 72) s_vk[tid] = 0.f;
    __syncthreads();

    float acc[72];
#pragma unroll
    for (int i = 0; i < 72; i++) acc[i] = 0.f;

    for (int n = tid; n < HW; n += 256) {
        float kv[8], vv[8];
#pragma unroll
        for (int e = 0; e < 8; e++) kv[e] = fmaxf(kp[(size_t)e * HW + n], 0.f);
#pragma unroll
        for (int d = 0; d < 8; d++) vv[d] = vp[(size_t)d * HW + n];
#pragma unroll
        for (int d = 0; d < 8; d++)
#pragma unroll
            for (int e = 0; e < 8; e++)
                acc[d * 8 + e] += vv[d] * kv[e];
#pragma unroll
        for (int e = 0; e < 8; e++) acc[64 + e] += kv[e];
    }

#pragma unroll
    for (int i = 0; i < 72; i++) {
        float v = acc[i];
        v += __shfl_down_sync(0xFFFFFFFFu, v, 16);
        v += __shfl_down_sync(0xFFFFFFFFu, v, 8);
        v += __shfl_down_sync(0xFFFFFFFFu, v, 4);
        v += __shfl_down_sync(0xFFFFFFFFu, v, 2);
        v += __shfl_down_sync(0xFFFFFFFFu, v, 1);
        if ((tid & 31) == 0) atomicAdd(&s_vk[i], v);
    }
    __syncthreads();

    float vk[72];
#pragma unroll
    for (int i = 0; i < 72; i++) vk[i] = s_vk[i];

    float* outp = att + ((size_t)b * 1024 + (size_t)h * 8) * HW;
    for (int n = tid; n < HW; n += 256) {
        float qv[8];
#pragma unroll
        for (int e = 0; e < 8; e++) qv[e] = fmaxf(qp[(size_t)e * HW + n], 0.f);
        float den = 0.f;
#pragma unroll
        for (int e = 0; e < 8; e++) den += vk[64 + e] * qv[e];
        float invd = 1.0f / (den + 1e-15f);
#pragma unroll
        for (int d = 0; d < 8; d++) {
            float o = 0.f;
#pragma unroll
            for (int e = 0; e < 8; e++) o += vk[d * 8 + e] * qv[e];
            outp[(size_t)d * HW + n] = o * invd;
        }
    }
}

// ---------------------------------------------------------------------------
extern "C" void kernel_launch(void* const* d_in, const int* in_sizes, int n_in,
                              void* d_out, int out_size)
{
    const float *x = nullptr, *w_qkv = nullptr, *w_dw = nullptr,
                *w_pw = nullptr, *w_proj = nullptr;
    for (int i = 0; i < n_in; i++) {
        switch (in_sizes[i]) {
            case 8388608: x      = (const float*)d_in[i]; break;
            case 786432:  w_qkv  = (const float*)d_in[i]; break;
            case 38400:   w_dw   = (const float*)d_in[i]; break;
            case 12288:   w_pw   = (const float*)d_in[i]; break;
            case 524288:  w_proj = (const float*)d_in[i]; break;
            default: break;
        }
    }
    if (!x || !w_qkv || !w_dw || !w_pw || !w_proj) {
        x      = (const float*)d_in[0];
        w_qkv  = (const float*)d_in[1];
        w_dw   = (const float*)d_in[2];
        w_pw   = (const float*)d_in[3];
        w_proj = (const float*)d_in[4];
    }
    float* out = (float*)d_out;

    float *qkv, *agg, *att;
    __nv_bfloat16 *xT3, *attT3, *wqkv3, *wproj3;
    cudaGetSymbolAddress((void**)&qkv,    g_qkv);
    cudaGetSymbolAddress((void**)&agg,    g_agg);
    cudaGetSymbolAddress((void**)&att,    g_att);
    cudaGetSymbolAddress((void**)&xT3,    g_xT3);
    cudaGetSymbolAddress((void**)&attT3,  g_attT3);
    cudaGetSymbolAddress((void**)&wqkv3,  g_wqkv3);
    cudaGetSymbolAddress((void**)&wproj3, g_wproj3);

    cudaFuncSetAttribute(mma_gemm, cudaFuncAttributeMaxDynamicSharedMemorySize,
                         GEMM_SMEM_BYTES);

    // Operand prep (bf16 hi/lo splits)
    w3_kernel<<<(1536 * 512 + 255) / 256, 256>>>(w_qkv, wqkv3, 512, 1536 * 512);
    w3_kernel<<<(512 * 1024 + 255) / 256, 256>>>(w_proj, wproj3, 1024, 512 * 1024);
    transpose_split<<<dim3(HW / 32, 512 / 32, BATCH), dim3(32, 8)>>>(x, xT3, 512);

    // 1) qkv = w_qkv @ x  : M=1536, N=4096, K3=1536
    mma_gemm<<<dim3(HW / 128, TD3 / 128, BATCH), 256, GEMM_SMEM_BYTES>>>(
        wqkv3, xT3, qkv, nullptr, TD3, HW, 1536);

    // 2) agg = grouped_pw(dw5x5(qkv))
    dwpw_kernel<<<dim3(4, 4, BATCH * 192), dim3(16, 16)>>>(qkv, w_dw, w_pw, agg);

    // 3) linear attention -> att (B,1024,HW)
    attn_kernel<<<BATCH * HEADS, 256>>>(qkv, agg, att);

    // prep att operand
    transpose_split<<<dim3(HW / 32, 1024 / 32, BATCH), dim3(32, 8)>>>(att, attT3, 1024);

    // 4) out = x + w_proj @ att : M=512, N=4096, K3=3072
    mma_gemm<<<dim3(HW / 128, 512 / 128, BATCH), 256, GEMM_SMEM_BYTES>>>(
        wproj3, attT3, out, x, 512, HW, 3072);
}

// round 15
// speedup vs baseline: 2.0264x; 1.0830x over previous
#include <cuda_runtime.h>
#include <cuda_bf16.h>
#include <cstdint>

// ---------------------------------------------------------------------------
// DCAELiteMLA on GB300: mma.sync bf16 3-term-split GEMMs (dedup [hi|lo]
// operands + chunk remap), fused dw/pw, split attention with fused
// transpose-to-GEMM-layout output.
// B=4, C=512, H=W=64 (HW=4096), td=512, DIM=8, heads=128, GROUPS_PW=192.
// ---------------------------------------------------------------------------

#define BATCH 4
#define HW    4096
#define TD3   1536
#define HEADS 128

// Scratch (__device__ globals; no allocation allowed)
__device__ float g_qkv[(size_t)BATCH * TD3 * HW];            // 96 MB
__device__ float g_agg[(size_t)BATCH * TD3 * HW];            // 96 MB
__device__ float g_vk [(size_t)BATCH * HEADS * 72];          // 147 KB
__device__ __nv_bfloat16 g_xT2  [(size_t)BATCH * HW * 1024]; // 33 MB [b][n][2*512]
__device__ __nv_bfloat16 g_attT2[(size_t)BATCH * HW * 2048]; // 67 MB [b][n][2*1024]
__device__ __nv_bfloat16 g_wqkv2 [(size_t)1536 * 1024];      // [m][2*512]
__device__ __nv_bfloat16 g_wproj2[(size_t)512 * 2048];       // [m][2*1024]

// ------------------------------- PTX helpers -------------------------------
__device__ __forceinline__ uint32_t smem_u32(const void* p) {
    uint32_t a;
    asm("{ .reg .u64 t; cvta.to.shared.u64 t, %1; cvt.u32.u64 %0, t; }"
        : "=r"(a) : "l"(p));
    return a;
}
#define CP_ASYNC16(saddr, gptr) \
    asm volatile("cp.async.cg.shared.global [%0], [%1], 16;" \
                 :: "r"((uint32_t)(saddr)), "l"(gptr) : "memory")
#define CP_ASYNC_COMMIT() asm volatile("cp.async.commit_group;" ::: "memory")
#define CP_ASYNC_WAIT0()  asm volatile("cp.async.wait_group 0;" ::: "memory")
#define CP_ASYNC_WAIT1()  asm volatile("cp.async.wait_group 1;" ::: "memory")
#define SW128(off) ((off) ^ (((off) >> 3) & 0x70))

__device__ __forceinline__ void ldsm4(uint32_t& r0, uint32_t& r1, uint32_t& r2,
                                      uint32_t& r3, uint32_t addr) {
    asm volatile("ldmatrix.sync.aligned.m8n8.x4.shared.b16 {%0,%1,%2,%3}, [%4];"
                 : "=r"(r0), "=r"(r1), "=r"(r2), "=r"(r3) : "r"(addr));
}
__device__ __forceinline__ void mma16816(float* c, const uint32_t* a,
                                         uint32_t b0, uint32_t b1) {
    asm volatile("mma.sync.aligned.m16n8k16.row.col.f32.bf16.bf16.f32 "
                 "{%0,%1,%2,%3}, {%4,%5,%6,%7}, {%8,%9}, {%0,%1,%2,%3};"
                 : "+f"(c[0]), "+f"(c[1]), "+f"(c[2]), "+f"(c[3])
                 : "r"(a[0]), "r"(a[1]), "r"(a[2]), "r"(a[3]), "r"(b0), "r"(b1));
}

// ---------------------------------------------------------------------------
// mma.sync GEMM with dedup 2-plane operands.
// C[b](MxN,f32) = sum over 3 virtual terms of A2(M x 2K bf16 [hi|lo]) @
// B2[b]^T (N x 2K bf16 [hi|lo]); virtual schedule [Ahi*Bhi, Alo*Bhi, Ahi*Blo]
// realized by chunk remap: nkh = K/64; nk = 3*nkh;
//   a_kc = kc < 2*nkh ? kc : kc - 2*nkh      (hi..lo..hi)
//   b_kc = kc <   nkh ? kc : kc - nkh        (hi..hi..lo)
// CTA tile 128x128, K-chunk 64, 3 stages x 32KB, wait_group 1,
// 256 thr = 8 warps 2x4, warp tile 64x32, launch_bounds(256,2).
// ---------------------------------------------------------------------------
#define STAGE_BYTES 32768
#define GEMM_SMEM_BYTES (3 * STAGE_BYTES + 1024)
__global__ __launch_bounds__(256, 2)
void mma_gemm(const __nv_bfloat16* __restrict__ A2,
              const __nv_bfloat16* __restrict__ B2,
              float* __restrict__ C, const float* __restrict__ R,
              int M, int N, int K)
{
    extern __shared__ char dsm_raw[];
    const uint32_t smem = (smem_u32(dsm_raw) + 1023u) & ~1023u;

    const int tid  = threadIdx.x;
    const int wid  = tid >> 5;
    const int lane = tid & 31;
    const int nkh  = K >> 6;
    const int nk   = 3 * nkh;
    const int K2   = 2 * K;

    const __nv_bfloat16* Abase = A2 + (size_t)blockIdx.y * 128 * K2;
    const __nv_bfloat16* Bbase = B2 + ((size_t)blockIdx.z * N
                               + (size_t)blockIdx.x * 128) * K2;

    const int ur = tid >> 3;      // 0..31 row group
    const int uu = tid & 7;       // 16B unit within 128B row

    auto prefetch = [&](int kc, int st) {
        const int a_kc = (kc < 2 * nkh) ? kc : kc - 2 * nkh;
        const int b_kc = (kc < nkh)     ? kc : kc - nkh;
        const uint32_t sa = smem + (uint32_t)st * STAGE_BYTES;
        const uint32_t sb = sa + 16384u;
        const __nv_bfloat16* ga = Abase + (size_t)a_kc * 64;
        const __nv_bfloat16* gb = Bbase + (size_t)b_kc * 64;
#pragma unroll
        for (int i = 0; i < 4; i++) {
            const int row = i * 32 + ur;
            const uint32_t sw = SW128((uint32_t)row * 128u + (uint32_t)uu * 16u);
            CP_ASYNC16(sa + sw, ga + (size_t)row * K2 + uu * 8);
            CP_ASYNC16(sb + sw, gb + (size_t)row * K2 + uu * 8);
        }
        CP_ASYNC_COMMIT();
    };

    float acc[4][4][4];
#pragma unroll
    for (int i = 0; i < 4; i++)
#pragma unroll
        for (int j = 0; j < 4; j++)
#pragma unroll
            for (int t = 0; t < 4; t++) acc[i][j][t] = 0.f;

    const int wm = wid >> 2;          // 0..1
    const int wn = wid & 3;           // 0..3
    const int mbase = wm * 64;
    const int nbase = wn * 32;
    const int sel = lane >> 3;        // ldmatrix matrix index
    const int l7  = lane & 7;

    prefetch(0, 0);
    prefetch(1, 1);

    for (int kc = 0; kc < nk; kc++) {
        if (kc + 1 < nk) { CP_ASYNC_WAIT1(); } else { CP_ASYNC_WAIT0(); }
        __syncthreads();
        if (kc + 2 < nk) prefetch(kc + 2, (kc + 2) % 3);

        const uint32_t sa = smem + (uint32_t)(kc % 3) * STAGE_BYTES;
        const uint32_t sb = sa + 16384u;

#pragma unroll
        for (int ks = 0; ks < 4; ks++) {            // 4 x k16 per 64-chunk
            uint32_t af[4][4], bfr[2][4];
#pragma unroll
            for (int i = 0; i < 4; i++) {
                const int row = mbase + i * 16 + (sel & 1) * 8 + l7;
                const uint32_t kb = (uint32_t)ks * 32u + (uint32_t)(sel >> 1) * 16u;
                ldsm4(af[i][0], af[i][1], af[i][2], af[i][3],
                      sa + SW128((uint32_t)row * 128u + kb));
            }
#pragma unroll
            for (int j = 0; j < 2; j++) {
                const int row = nbase + j * 16 + (sel >> 1) * 8 + l7;
                const uint32_t kb = (uint32_t)ks * 32u + (uint32_t)(sel & 1) * 16u;
                ldsm4(bfr[j][0], bfr[j][1], bfr[j][2], bfr[j][3],
                      sb + SW128((uint32_t)row * 128u + kb));
            }
#pragma unroll
            for (int i = 0; i < 4; i++)
#pragma unroll
                for (int jj = 0; jj < 4; jj++)
                    mma16816(acc[i][jj], af[i],
                             bfr[jj >> 1][(jj & 1) * 2],
                             bfr[jj >> 1][(jj & 1) * 2 + 1]);
        }
    }

    const int g   = lane >> 2;
    const int tig = lane & 3;
    const size_t cbz = (size_t)blockIdx.z * M;
#pragma unroll
    for (int i = 0; i < 4; i++) {
#pragma unroll
        for (int jj = 0; jj < 4; jj++) {
            const int row0 = blockIdx.y * 128 + mbase + i * 16 + g;
            const int col  = blockIdx.x * 128 + nbase + jj * 8 + 2 * tig;
            float* p0 = C + (cbz + row0) * N + col;
            float* p1 = C + (cbz + row0 + 8) * N + col;
            float2 v0 = make_float2(acc[i][jj][0], acc[i][jj][1]);
            float2 v1 = make_float2(acc[i][jj][2], acc[i][jj][3]);
            if (R) {
                const float2 r0 = *(const float2*)(R + (cbz + row0) * N + col);
                const float2 r1 = *(const float2*)(R + (cbz + row0 + 8) * N + col);
                v0.x += r0.x; v0.y += r0.y;
                v1.x += r1.x; v1.y += r1.y;
            }
            *(float2*)p0 = v0;
            *(float2*)p1 = v1;
        }
    }
}

// ---------------------------------------------------------------------------
// A-side weight split: in [M][K] f32 -> out [M][2K] bf16 as [hi | lo]
// ---------------------------------------------------------------------------
__global__ void w2_kernel(const float* __restrict__ in, __nv_bfloat16* __restrict__ out,
                          int K, int total)
{
    int idx = blockIdx.x * blockDim.x + threadIdx.x;
    if (idx >= total) return;
    int m = idx / K, k = idx - m * K;
    float v = in[idx];
    __nv_bfloat16 hi = __float2bfloat16(v);
    __nv_bfloat16 lo = __float2bfloat16(v - __bfloat162float(hi));
    __nv_bfloat16* o = out + (size_t)m * 2 * K;
    o[k] = hi; o[K + k] = lo;
}

// ---------------------------------------------------------------------------
// B-side transpose+split: in [b][C][HW] f32 -> out [b][HW][2C] bf16 [hi|lo]
// ---------------------------------------------------------------------------
__global__ void transpose_split(const float* __restrict__ in,
                                __nv_bfloat16* __restrict__ out, int C)
{
    __shared__ float t[32][33];
    const int bz = blockIdx.z;
    const float* inb = in + (size_t)bz * C * HW;
    __nv_bfloat16* ob = out + (size_t)bz * HW * 2 * C;
    const int tx = threadIdx.x, ty = threadIdx.y;
    const int k0 = blockIdx.y * 32, n0 = blockIdx.x * 32;
#pragma unroll
    for (int i = 0; i < 4; i++)
        t[ty + i * 8][tx] = inb[(size_t)(k0 + ty + i * 8) * HW + n0 + tx];
    __syncthreads();
    const int k = k0 + tx;
#pragma unroll
    for (int i = 0; i < 4; i++) {
        const int n = n0 + ty + i * 8;
        float v = t[tx][ty + i * 8];
        __nv_bfloat16 hi = __float2bfloat16(v);
        __nv_bfloat16 lo = __float2bfloat16(v - __bfloat162float(hi));
        __nv_bfloat16* o = ob + (size_t)n * 2 * C;
        o[k] = hi; o[C + k] = lo;
    }
}

// ---------------------------------------------------------------------------
// Fused depthwise 5x5 (pad=2) + grouped 1x1 (192 groups, 8->8). Unchanged.
// ---------------------------------------------------------------------------
__global__ __launch_bounds__(256)
void dwpw_kernel(const float* __restrict__ qkv, const float* __restrict__ wdw,
                 const float* __restrict__ wpw, float* __restrict__ agg)
{
    __shared__ float s_in[8][20][20];
    __shared__ float s_wdw[8][25];
    __shared__ float s_wpw[8][8];

    const int tid = threadIdx.y * 16 + threadIdx.x;
    const int bz  = blockIdx.z;
    const int b   = bz / 192;
    const int g   = bz - b * 192;
    const int x0  = blockIdx.x * 16;
    const int y0  = blockIdx.y * 16;

    const float* inb = qkv + ((size_t)b * TD3 + (size_t)g * 8) * HW;

    for (int i = tid; i < 8 * 25; i += 256)
        s_wdw[i / 25][i % 25] = wdw[(g * 8 + i / 25) * 25 + (i % 25)];
    if (tid < 64)
        s_wpw[tid >> 3][tid & 7] = wpw[(g * 8 + (tid >> 3)) * 8 + (tid & 7)];

    for (int idx = tid; idx < 8 * 400; idx += 256) {
        int c  = idx / 400;
        int p  = idx - c * 400;
        int iy = p / 20;
        int ix = p - iy * 20;
        int gy = y0 + iy - 2;
        int gx = x0 + ix - 2;
        float v = 0.f;
        if (gy >= 0 && gy < 64 && gx >= 0 && gx < 64)
            v = inb[(size_t)c * HW + gy * 64 + gx];
        s_in[c][iy][ix] = v;
    }
    __syncthreads();

    const int txx = threadIdx.x, tyy = threadIdx.y;
    float dw[8];
#pragma unroll
    for (int c = 0; c < 8; c++) {
        float s = 0.f;
#pragma unroll
        for (int dy = 0; dy < 5; dy++)
#pragma unroll
            for (int dx = 0; dx < 5; dx++)
                s += s_wdw[c][dy * 5 + dx] * s_in[c][tyy + dy][txx + dx];
        dw[c] = s;
    }

    float* outb = agg + ((size_t)b * TD3 + (size_t)g * 8) * HW
                      + (y0 + tyy) * 64 + (x0 + txx);
#pragma unroll
    for (int o = 0; o < 8; o++) {
        float s = 0.f;
#pragma unroll
        for (int i = 0; i < 8; i++) s += s_wpw[o][i] * dw[i];
        outb[(size_t)o * HW] = s;
    }
}

// ---------------------------------------------------------------------------
// Attention pass 1: per (b,head) vk reduction -> g_vk[bh][72].
// ---------------------------------------------------------------------------
__global__ __launch_bounds__(256)
void attn_vk_kernel(const float* __restrict__ qkvbuf, const float* __restrict__ aggbuf,
                    float* __restrict__ vkbuf)
{
    const int bh = blockIdx.x;
    const int b  = bh >> 7;
    const int h  = bh & 127;
    const float* src = (h < 64) ? qkvbuf : aggbuf;
    const int    hh  = (h < 64) ? h : h - 64;
    const float* base = src + ((size_t)b * TD3 + (size_t)hh * 24) * HW;
    const float* kp = base + (size_t)8 * HW;
    const float* vp = base + (size_t)16 * HW;

    __shared__ float s_vk[72];
    const int tid = threadIdx.x;
    if (tid < 72) s_vk[tid] = 0.f;
    __syncthreads();

    float acc[72];
#pragma unroll
    for (int i = 0; i < 72; i++) acc[i] = 0.f;

    for (int n = tid; n < HW; n += 256) {
        float kv[8], vv[8];
#pragma unroll
        for (int e = 0; e < 8; e++) kv[e] = fmaxf(kp[(size_t)e * HW + n], 0.f);
#pragma unroll
        for (int d = 0; d < 8; d++) vv[d] = vp[(size_t)d * HW + n];
#pragma unroll
        for (int d = 0; d < 8; d++)
#pragma unroll
            for (int e = 0; e < 8; e++)
                acc[d * 8 + e] += vv[d] * kv[e];
#pragma unroll
        for (int e = 0; e < 8; e++) acc[64 + e] += kv[e];
    }

#pragma unroll
    for (int i = 0; i < 72; i++) {
        float v = acc[i];
        v += __shfl_down_sync(0xFFFFFFFFu, v, 16);
        v += __shfl_down_sync(0xFFFFFFFFu, v, 8);
        v += __shfl_down_sync(0xFFFFFFFFu, v, 4);
        v += __shfl_down_sync(0xFFFFFFFFu, v, 2);
        v += __shfl_down_sync(0xFFFFFFFFu, v, 1);
        if ((tid & 31) == 0) atomicAdd(&s_vk[i], v);
    }
    __syncthreads();
    if (tid < 72) vkbuf[(size_t)bh * 72 + tid] = s_vk[tid];
}

// ---------------------------------------------------------------------------
// Attention pass 2 + transpose: computes out[c][n] for a (b, 32-head group,
// 32-n tile) and writes it directly in the proj-GEMM B layout
// attT2[b][n][2048] = [hi(1024) | lo(1024)], coalesced via smem staging.
// 256 threads = 8 warps; warp w handles heads hg*32 + w*4 .. +3, lane = n.
// ---------------------------------------------------------------------------
__global__ __launch_bounds__(256)
void attn_out_kernel(const float* __restrict__ qkvbuf, const float* __restrict__ aggbuf,
                     const float* __restrict__ vkbuf, __nv_bfloat16* __restrict__ attT2)
{
    __shared__ float s_vk[32][72];
    __shared__ __align__(16) __nv_bfloat16 s_hi[32][264];  // [n][c], 528B rows
    __shared__ __align__(16) __nv_bfloat16 s_lo[32][264];

    const int n0 = blockIdx.x * 32;
    const int hg = blockIdx.y;            // 0..3 (32 heads each)
    const int b  = blockIdx.z;
    const int tid  = threadIdx.x;
    const int warp = tid >> 5;
    const int lane = tid & 31;

    for (int i = tid; i < 32 * 72; i += 256) {
        const int idx = i / 72, j = i - idx * 72;
        s_vk[idx][j] = vkbuf[((size_t)(b * HEADS + hg * 32 + idx)) * 72 + j];
    }
    __syncthreads();

    const int n = n0 + lane;
#pragma unroll
    for (int hh = 0; hh < 4; hh++) {
        const int idx = warp * 4 + hh;            // 0..31 within group
        const int h   = hg * 32 + idx;            // global head
        const float* src = (h < 64) ? qkvbuf : aggbuf;
        const int    hq  = (h < 64) ? h : h - 64;
        const float* qp  = src + ((size_t)b * TD3 + (size_t)hq * 24) * HW;

        float qv[8];
#pragma unroll
        for (int e = 0; e < 8; e++) qv[e] = fmaxf(qp[(size_t)e * HW + n], 0.f);

        float den = 0.f;
#pragma unroll
        for (int e = 0; e < 8; e++) den += s_vk[idx][64 + e] * qv[e];
        const float invd = 1.0f / (den + 1e-15f);

#pragma unroll
        for (int d = 0; d < 8; d++) {
            float o = 0.f;
#pragma unroll
            for (int e = 0; e < 8; e++) o += s_vk[idx][d * 8 + e] * qv[e];
            o *= invd;
            const __nv_bfloat16 hi = __float2bfloat16(o);
            const __nv_bfloat16 lo = __float2bfloat16(o - __bfloat162float(hi));
            const int c = idx * 8 + d;            // 0..255
            s_hi[lane][c] = hi;
            s_lo[lane][c] = lo;
        }
    }
    __syncthreads();

    // Write out: per n, 256 channels = 32 uint4 per plane, coalesced.
    for (int i = tid; i < 32 * 32; i += 256) {
        const int nn = i >> 5;                    // 0..31
        const int v  = i & 31;                    // uint4 index (8 ch)
        __nv_bfloat16* row = attT2 + ((size_t)b * HW + (n0 + nn)) * 2048;
        ((uint4*)(row + hg * 256))[v]        = ((const uint4*)&s_hi[nn][0])[v];
        ((uint4*)(row + 1024 + hg * 256))[v] = ((const uint4*)&s_lo[nn][0])[v];
    }
}

// ---------------------------------------------------------------------------
extern "C" void kernel_launch(void* const* d_in, const int* in_sizes, int n_in,
                              void* d_out, int out_size)
{
    const float *x = nullptr, *w_qkv = nullptr, *w_dw = nullptr,
                *w_pw = nullptr, *w_proj = nullptr;
    for (int i = 0; i < n_in; i++) {
        switch (in_sizes[i]) {
            case 8388608: x      = (const float*)d_in[i]; break;
            case 786432:  w_qkv  = (const float*)d_in[i]; break;
            case 38400:   w_dw   = (const float*)d_in[i]; break;
            case 12288:   w_pw   = (const float*)d_in[i]; break;
            case 524288:  w_proj = (const float*)d_in[i]; break;
            default: break;
        }
    }
    if (!x || !w_qkv || !w_dw || !w_pw || !w_proj) {
        x      = (const float*)d_in[0];
        w_qkv  = (const float*)d_in[1];
        w_dw   = (const float*)d_in[2];
        w_pw   = (const float*)d_in[3];
        w_proj = (const float*)d_in[4];
    }
    float* out = (float*)d_out;

    float *qkv, *agg, *vkb;
    __nv_bfloat16 *xT2, *attT2, *wqkv2, *wproj2;
    cudaGetSymbolAddress((void**)&qkv,    g_qkv);
    cudaGetSymbolAddress((void**)&agg,    g_agg);
    cudaGetSymbolAddress((void**)&vkb,    g_vk);
    cudaGetSymbolAddress((void**)&xT2,    g_xT2);
    cudaGetSymbolAddress((void**)&attT2,  g_attT2);
    cudaGetSymbolAddress((void**)&wqkv2,  g_wqkv2);
    cudaGetSymbolAddress((void**)&wproj2, g_wproj2);

    cudaFuncSetAttribute(mma_gemm, cudaFuncAttributeMaxDynamicSharedMemorySize,
                         GEMM_SMEM_BYTES);

    // Operand prep (bf16 hi/lo splits, dedup 2-plane layout)
    w2_kernel<<<(1536 * 512 + 255) / 256, 256>>>(w_qkv, wqkv2, 512, 1536 * 512);
    w2_kernel<<<(512 * 1024 + 255) / 256, 256>>>(w_proj, wproj2, 1024, 512 * 1024);
    transpose_split<<<dim3(HW / 32, 512 / 32, BATCH), dim3(32, 8)>>>(x, xT2, 512);

    // 1) qkv = w_qkv @ x  : M=1536, N=4096, K=512 (virtual K3=1536)
    mma_gemm<<<dim3(HW / 128, TD3 / 128, BATCH), 256, GEMM_SMEM_BYTES>>>(
        wqkv2, xT2, qkv, nullptr, TD3, HW, 512);

    // 2) agg = grouped_pw(dw5x5(qkv))
    dwpw_kernel<<<dim3(4, 4, BATCH * 192), dim3(16, 16)>>>(qkv, w_dw, w_pw, agg);

    // 3) linear attention: vk reduction, then out + fused transpose/split
    attn_vk_kernel<<<BATCH * HEADS, 256>>>(qkv, agg, vkb);
    attn_out_kernel<<<dim3(HW / 32, 4, BATCH), 256>>>(qkv, agg, vkb, attT2);

    // 4) out = x + w_proj @ att : M=512, N=4096, K=1024 (virtual K3=3072)
    mma_gemm<<<dim3(HW / 128, 512 / 128, BATCH), 256, GEMM_SMEM_BYTES>>>(
        wproj2, attT2, out, x, 512, HW, 1024);
}